// round 17
// baseline (speedup 1.0000x reference)
#include <cuda_runtime.h>
#include <cstdint>

constexpr int B_ = 64, C_ = 512, NE_ = 80, NI_ = 20, E_ = 512;
#define DTC 0.1f

// f32 cp.async ring (producer-private rows): A[64 x 36f] + W[80 x 36f]
constexpr int LDF    = 144;                 // bytes per f32 row (36 floats)
constexpr int F_A    = 64 * LDF;            // 9216
constexpr int F_SLOT = F_A + 80 * LDF;      // 20736
constexpr int NF     = 3;
// bf16 ldmatrix ring: A [64 x 32] + W [80 x 32], row stride 80 bytes
constexpr int LDB     = 80;
constexpr int A_BYTES = 64 * LDB;           // 5120
constexpr int BF_SLOT = A_BYTES + 80 * LDB; // 11520
constexpr int NB      = 3;
constexpr int BF_OFF  = NF * F_SLOT;        // 62208
constexpr int LDWEI   = 96;
constexpr int WEI_OFF = BF_OFF + NB * BF_SLOT;        // 96768
constexpr int SMEM_BYTES = WEI_OFF + 20 * LDWEI * 4;  // 104448

constexpr size_t OFF_RI = (size_t)B_ * C_ * NE_;
constexpr size_t OFF_VE = OFF_RI + (size_t)B_ * C_ * NI_;
constexpr size_t OFF_VI = OFF_VE + (size_t)B_ * C_ * NE_;

// named barriers (count 320): 0 = init, FULL(s)=1+s, EMPTY(s)=4+s
#define BSYNC(id) asm volatile("bar.sync %0, 320;"   :: "r"(id) : "memory")
#define BARR(id)  asm volatile("bar.arrive %0, 320;" :: "r"(id) : "memory")

__device__ __forceinline__ uint32_t s2u(const void* p) {
    uint32_t a;
    asm("{ .reg .u64 t; cvta.to.shared.u64 t, %1; cvt.u32.u64 %0, t; }" : "=r"(a) : "l"(p));
    return a;
}
__device__ __forceinline__ void cpa16(uint32_t dst, const float* src) {
    asm volatile("cp.async.cg.shared.global [%0], [%1], 16;" :: "r"(dst), "l"(src));
}
__device__ __forceinline__ void cpa16z(uint32_t dst, const float* src) {
    asm volatile("cp.async.cg.shared.global [%0], [%1], 16, 0;" :: "r"(dst), "l"(src));
}
#define CP_COMMIT() asm volatile("cp.async.commit_group;" ::: "memory")
#define CP_WAIT2()  asm volatile("cp.async.wait_group 2;" ::: "memory")
#define CP_WAIT1()  asm volatile("cp.async.wait_group 1;" ::: "memory")
#define CP_WAIT0()  asm volatile("cp.async.wait_group 0;" ::: "memory")

__device__ __forceinline__ uint32_t bfx2(float2 f) {
    uint32_t r;
    asm("cvt.rn.bf16x2.f32 %0, %1, %2;" : "=r"(r) : "f"(f.y), "f"(f.x));
    return r;
}
__device__ __forceinline__ void sts16(uint32_t a, float4 x, float4 y) {
    uint32_t u0 = bfx2(make_float2(x.x, x.y)), u1 = bfx2(make_float2(x.z, x.w));
    uint32_t u2 = bfx2(make_float2(y.x, y.y)), u3 = bfx2(make_float2(y.z, y.w));
    asm volatile("st.shared.v4.b32 [%0], {%1,%2,%3,%4};"
                 :: "r"(a), "r"(u0), "r"(u1), "r"(u2), "r"(u3) : "memory");
}
__device__ __forceinline__ void ldsm4(uint32_t r[4], uint32_t addr) {
    asm volatile("ldmatrix.sync.aligned.m8n8.x4.shared.b16 {%0,%1,%2,%3}, [%4];"
        : "=r"(r[0]), "=r"(r[1]), "=r"(r[2]), "=r"(r[3]) : "r"(addr));
}
__device__ __forceinline__ void mma16(float d[4], uint32_t a0, uint32_t a1,
                                      uint32_t a2, uint32_t a3,
                                      uint32_t b0, uint32_t b1) {
    asm("mma.sync.aligned.m16n8k16.row.col.f32.bf16.bf16.f32 "
        "{%0,%1,%2,%3}, {%4,%5,%6,%7}, {%8,%9}, {%0,%1,%2,%3};"
        : "+f"(d[0]), "+f"(d[1]), "+f"(d[2]), "+f"(d[3])
        : "r"(a0), "r"(a1), "r"(a2), "r"(a3), "r"(b0), "r"(b1));
}

// chunk table:
// k 0-15 : I_ext k0=k*32 (A=thal_inc + thal folded in bounce, W=input_proj)
// k 16-18: I_fb  k0=(k-16)*32 (A=l23_fb, W=feedback_proj; cols>=80 zero)
// k 19-21: I_ee  k0=(k-19)*32 (A=r_e, W=W_ee; cols>=80 zero) + I_ei via Wei
// k 22   : I_ie  K=20 pad 32 (A=r_i negated in bounce, W=W_ie)

// producer: cp.async chunk k (thread p owns A row p, W rows p and 64+p)
__device__ __forceinline__ void cpa_chunk(
    int k, int c, int p, uint32_t smb,
    const float* thal_inc, const float* l23_fb, const float* r_e,
    const float* r_i, const float* input_proj, const float* feedback_proj,
    const float* W_ee, const float* W_ie) {
    const uint32_t fb = smb + (k % NF) * F_SLOT;
    if (k < 16) {
        const int k0 = k * 32;
        const float* a = thal_inc + ((size_t)p * C_ + c) * E_ + k0;
        const float* w0 = input_proj + ((size_t)c * NE_ + p) * E_ + k0;
#pragma unroll
        for (int j = 0; j < 8; j++) {
            cpa16(fb + p * LDF + j * 16, a + j * 4);
            cpa16(fb + F_A + p * LDF + j * 16, w0 + j * 4);
        }
        if (p < 16) {
            const float* w1 = input_proj + ((size_t)c * NE_ + 64 + p) * E_ + k0;
#pragma unroll
            for (int j = 0; j < 8; j++)
                cpa16(fb + F_A + (64 + p) * LDF + j * 16, w1 + j * 4);
        }
    } else if (k < 22) {
        const bool isB = k < 19;
        const int k0 = (k - (isB ? 16 : 19)) * 32;
        const float* Ap = isB ? l23_fb : r_e;
        const float* Wp = isB ? feedback_proj : W_ee;
        const float* a = Ap + ((size_t)p * C_ + c) * NE_;
        const float* w0 = Wp + ((size_t)c * NE_ + p) * NE_;
#pragma unroll
        for (int j = 0; j < 8; j++) {
            const int col = k0 + j * 4;
            if (col < NE_) cpa16(fb + p * LDF + j * 16, a + col);
            else           cpa16z(fb + p * LDF + j * 16, a);
            if (col < NE_) cpa16(fb + F_A + p * LDF + j * 16, w0 + col);
            else           cpa16z(fb + F_A + p * LDF + j * 16, w0);
        }
        if (p < 16) {
            const float* w1 = Wp + ((size_t)c * NE_ + 64 + p) * NE_;
#pragma unroll
            for (int j = 0; j < 8; j++) {
                const int col = k0 + j * 4;
                if (col < NE_) cpa16(fb + F_A + (64 + p) * LDF + j * 16, w1 + col);
                else           cpa16z(fb + F_A + (64 + p) * LDF + j * 16, w1);
            }
        }
    } else {
        const float* a = r_i + ((size_t)p * C_ + c) * NI_;
        const float* w0 = W_ie + ((size_t)c * NE_ + p) * NI_;
#pragma unroll
        for (int j = 0; j < 8; j++) {
            if (j < 5) cpa16(fb + p * LDF + j * 16, a + j * 4);
            else       cpa16z(fb + p * LDF + j * 16, a);
            if (j < 5) cpa16(fb + F_A + p * LDF + j * 16, w0 + j * 4);
            else       cpa16z(fb + F_A + p * LDF + j * 16, w0);
        }
        if (p < 16) {
            const float* w1 = W_ie + ((size_t)c * NE_ + 64 + p) * NI_;
#pragma unroll
            for (int j = 0; j < 8; j++) {
                if (j < 5) cpa16(fb + F_A + (64 + p) * LDF + j * 16, w1 + j * 4);
                else       cpa16z(fb + F_A + (64 + p) * LDF + j * 16, w1);
            }
        }
    }
}

// producer: f32 slot -> (thal fold / negate) -> bf16 slot. All same-thread rows.
__device__ __forceinline__ void bounce(int k, int p, char* smp, uint32_t smb,
                                       const float* thal) {
    const char* fbp = smp + (k % NF) * F_SLOT;
    const uint32_t bb = smb + BF_OFF + (k % NB) * BF_SLOT;
    // A row p
#pragma unroll 2
    for (int j = 0; j < 4; j++) {
        float4 x = *(const float4*)(fbp + p * LDF + (2 * j) * 16);
        float4 y = *(const float4*)(fbp + p * LDF + (2 * j + 1) * 16);
        if (k < 16) {
            const float* tp = thal + (size_t)p * E_ + k * 32 + j * 8;
            float4 tx = __ldg((const float4*)tp);
            float4 ty = __ldg((const float4*)(tp + 4));
            x.x += tx.x; x.y += tx.y; x.z += tx.z; x.w += tx.w;
            y.x += ty.x; y.y += ty.y; y.z += ty.z; y.w += ty.w;
        } else if (k == 22) {
            x.x = -x.x; x.y = -x.y; x.z = -x.z; x.w = -x.w;
            y.x = -y.x; y.y = -y.y; y.z = -y.z; y.w = -y.w;
        }
        sts16(bb + p * LDB + j * 16, x, y);
    }
    // W rows p and 64+p (p<16)
#pragma unroll
    for (int r = 0; r < 2; r++) {
        const int u = p + 64 * r;
        if (r == 0 || p < 16) {
#pragma unroll 2
            for (int j = 0; j < 4; j++) {
                float4 x = *(const float4*)(fbp + F_A + u * LDF + (2 * j) * 16);
                float4 y = *(const float4*)(fbp + F_A + u * LDF + (2 * j + 1) * 16);
                sts16(bb + A_BYTES + u * LDB + j * 16, x, y);
            }
        }
    }
}

__global__ void __launch_bounds__(320, 2)
ei_pc(const float* __restrict__ thal, const float* __restrict__ thal_inc,
      const float* __restrict__ l23_fb, const float* __restrict__ r_e,
      const float* __restrict__ r_i, const float* __restrict__ e_v,
      const float* __restrict__ i_v, const float* __restrict__ input_proj,
      const float* __restrict__ feedback_proj, const float* __restrict__ W_ee,
      const float* __restrict__ W_ei, const float* __restrict__ W_ie,
      float* __restrict__ out) {
    extern __shared__ char smp[];
    const uint32_t smb = s2u(smp);
    const int t = threadIdx.x, c = blockIdx.x;

    if (t >= 256) {
        // ================= PRODUCER (warps 8,9) =================
        const int p = t - 256;
        cpa_chunk(0, c, p, smb, thal_inc, l23_fb, r_e, r_i, input_proj, feedback_proj, W_ee, W_ie);
        CP_COMMIT();
        cpa_chunk(1, c, p, smb, thal_inc, l23_fb, r_e, r_i, input_proj, feedback_proj, W_ee, W_ie);
        CP_COMMIT();
        cpa_chunk(2, c, p, smb, thal_inc, l23_fb, r_e, r_i, input_proj, feedback_proj, W_ee, W_ie);
        CP_COMMIT();
        BSYNC(0);
#pragma unroll 1
        for (int k = 0; k < 23; k++) {
            if (k >= 3) BSYNC(4 + k % 3);            // wait slot empty
            if (k < 21) CP_WAIT2(); else if (k == 21) CP_WAIT1(); else CP_WAIT0();
            bounce(k, p, smp, smb, thal);
            asm volatile("membar.cta;" ::: "memory");
            BARR(1 + k % 3);                         // mark slot full
            if (k + 3 <= 22) {
                cpa_chunk(k + 3, c, p, smb, thal_inc, l23_fb, r_e, r_i,
                          input_proj, feedback_proj, W_ee, W_ie);
                CP_COMMIT();
            }
        }
        return;
    }

    // ================= CONSUMER (warps 0-7) =================
    const int w = t >> 5, lane = t & 31;
    const int wm = w >> 1, wn = w & 1;
    const int m0 = wm * 16, lm = lane >> 2, lc = lane & 3;

    float accE[5][4], accI[3][4];
#pragma unroll
    for (int j = 0; j < 5; j++)
#pragma unroll
        for (int q = 0; q < 4; q++) accE[j][q] = 0.f;
#pragma unroll
    for (int j = 0; j < 3; j++)
#pragma unroll
        for (int q = 0; q < 4; q++) accI[j][q] = 0.f;

    // persistent W_ei f32 buffer (20 rows x 96, cols >=80 zero)
    for (int idx = t; idx < 480; idx += 256) {
        int row = idx / 24, g = idx % 24;
        float4 v = make_float4(0.f, 0.f, 0.f, 0.f);
        if (g < 20) v = __ldg((const float4*)(W_ei + ((size_t)c * NI_ + row) * NE_ + g * 4));
        *(float4*)(smp + WEI_OFF + (row * LDWEI + g * 4) * 4) = v;
    }
    BSYNC(0);

    const float* Wei = (const float*)(smp + WEI_OFF);
    const bool wiv2 = (lm < 4);
    const uint32_t a_off = (uint32_t)((m0 + (lane & 7) + ((lane >> 3) & 1) * 8) * LDB
                                      + (lane >> 4) * 16);
    const uint32_t w_off = (uint32_t)(A_BYTES + (wn * 40 + (lane & 7)) * LDB
                                      + (lane >> 3) * 16);

#pragma unroll 1
    for (int k = 0; k < 23; k++) {
        BSYNC(1 + k % 3);                            // wait slot full
        const uint32_t base = smb + BF_OFF + (k % NB) * BF_SLOT;
        uint32_t Ak0[4], Ak1[4];
        ldsm4(Ak0, base + a_off);
        ldsm4(Ak1, base + a_off + 32);
#pragma unroll
        for (int j = 0; j < 5; j++) {
            uint32_t Bf[4];
            ldsm4(Bf, base + w_off + (uint32_t)(j * 8 * LDB));
            mma16(accE[j], Ak0[0], Ak0[1], Ak0[2], Ak0[3], Bf[0], Bf[1]);
            mma16(accE[j], Ak1[0], Ak1[1], Ak1[2], Ak1[3], Bf[2], Bf[3]);
        }
        if (k >= 19 && k <= 21 && wn == 0) {
            const int kei0 = (k - 19) * 32;
            const float2 z = make_float2(0.f, 0.f);
#pragma unroll
            for (int j = 0; j < 3; j++) {
                const bool v = (j < 2) || wiv2;
                const float* wp = Wei + (j * 8 + (v ? lm : 0)) * LDWEI + kei0 + 2 * lc;
                uint32_t b0 = bfx2(v ? *(const float2*)(wp) : z);
                uint32_t b1 = bfx2(v ? *(const float2*)(wp + 8) : z);
                mma16(accI[j], Ak0[0], Ak0[1], Ak0[2], Ak0[3], b0, b1);
                uint32_t b2 = bfx2(v ? *(const float2*)(wp + 16) : z);
                uint32_t b3 = bfx2(v ? *(const float2*)(wp + 24) : z);
                mma16(accI[j], Ak1[0], Ak1[1], Ak1[2], Ak1[3], b2, b3);
            }
        }
        if (k <= 19) BARR(4 + k % 3);                // mark slot empty
    }

    // ---------------- epilogue: leaky integration + relu ----------------
    const int r0 = m0 + lm, r1 = r0 + 8;
#pragma unroll
    for (int j = 0; j < 5; j++) {
        const int col = wn * 40 + j * 8 + 2 * lc;
        const size_t i0 = ((size_t)r0 * C_ + c) * NE_ + col;
        const size_t i1 = ((size_t)r1 * C_ + c) * NE_ + col;
        float2 ev0 = *(const float2*)(e_v + i0);
        float2 ev1 = *(const float2*)(e_v + i1);
        float v0x = ev0.x + DTC * (accE[j][0] - ev0.x);
        float v0y = ev0.y + DTC * (accE[j][1] - ev0.y);
        float v1x = ev1.x + DTC * (accE[j][2] - ev1.x);
        float v1y = ev1.y + DTC * (accE[j][3] - ev1.y);
        *(float2*)(out + i0)          = make_float2(fmaxf(v0x, 0.f), fmaxf(v0y, 0.f));
        *(float2*)(out + i1)          = make_float2(fmaxf(v1x, 0.f), fmaxf(v1y, 0.f));
        *(float2*)(out + OFF_VE + i0) = make_float2(v0x, v0y);
        *(float2*)(out + OFF_VE + i1) = make_float2(v1x, v1y);
    }
    if (wn == 0) {
#pragma unroll
        for (int j = 0; j < 3; j++) {
            const int col = j * 8 + 2 * lc;
            if (col < NI_) {
                const size_t i0 = ((size_t)r0 * C_ + c) * NI_ + col;
                const size_t i1 = ((size_t)r1 * C_ + c) * NI_ + col;
                float2 iv0 = *(const float2*)(i_v + i0);
                float2 iv1 = *(const float2*)(i_v + i1);
                float v0x = iv0.x + DTC * (accI[j][0] - iv0.x);
                float v0y = iv0.y + DTC * (accI[j][1] - iv0.y);
                float v1x = iv1.x + DTC * (accI[j][2] - iv1.x);
                float v1y = iv1.y + DTC * (accI[j][3] - iv1.y);
                *(float2*)(out + OFF_RI + i0) = make_float2(fmaxf(v0x, 0.f), fmaxf(v0y, 0.f));
                *(float2*)(out + OFF_RI + i1) = make_float2(fmaxf(v1x, 0.f), fmaxf(v1y, 0.f));
                *(float2*)(out + OFF_VI + i0) = make_float2(v0x, v0y);
                *(float2*)(out + OFF_VI + i1) = make_float2(v1x, v1y);
            }
        }
    }
}

extern "C" void kernel_launch(void* const* d_in, const int* in_sizes, int n_in,
                              void* d_out, int out_size) {
    (void)in_sizes; (void)n_in; (void)out_size;
    cudaFuncSetAttribute(ei_pc, cudaFuncAttributeMaxDynamicSharedMemorySize,
                         SMEM_BYTES);
    ei_pc<<<C_, 320, SMEM_BYTES>>>(
        (const float*)d_in[0],   // thal
        (const float*)d_in[1],   // thal_increments
        (const float*)d_in[2],   // l23_fb
        (const float*)d_in[3],   // r_e
        (const float*)d_in[4],   // r_i
        (const float*)d_in[5],   // e_v
        (const float*)d_in[6],   // i_v
        (const float*)d_in[7],   // input_proj
        (const float*)d_in[8],   // feedback_proj
        (const float*)d_in[9],   // W_ee
        (const float*)d_in[10],  // W_ei
        (const float*)d_in[11],  // W_ie
        (float*)d_out);
}